// round 1
// baseline (speedup 1.0000x reference)
#include <cuda_runtime.h>

#define TPB 256

__global__ __launch_bounds__(TPB) void tp_kernel(
    const float* __restrict__ x0, const float* __restrict__ y0,
    const float* __restrict__ x1, const float* __restrict__ y1,
    const float* __restrict__ x2, const float* __restrict__ y2,
    float* __restrict__ out, long long NC)
{
    __shared__ float sA[TPB * 9];
    __shared__ float sB[TPB * 9];
    __shared__ float su[TPB * 3];
    __shared__ float sv[TPB * 3];
    __shared__ float sa[TPB];
    __shared__ float sb[TPB];

    const long long base = (long long)blockIdx.x * TPB;
    const int t = threadIdx.x;
    long long rem = NC - base;
    const int npair = rem < TPB ? (int)rem : TPB;
    const bool full = (npair == TPB);

    // ---- Stage inputs into smem (fully coalesced float4 on the full-block path) ----
    if (full) {
        {
            const float4* gA = (const float4*)(x2 + base * 9);
            const float4* gB = (const float4*)(y2 + base * 9);
            float4* s4a = (float4*)sA;
            float4* s4b = (float4*)sB;
            #pragma unroll
            for (int i = t; i < TPB * 9 / 4; i += TPB) { s4a[i] = gA[i]; s4b[i] = gB[i]; }
        }
        {
            const float4* gu = (const float4*)(x1 + base * 3);
            const float4* gv = (const float4*)(y1 + base * 3);
            float4* s4u = (float4*)su;
            float4* s4v = (float4*)sv;
            #pragma unroll
            for (int i = t; i < TPB * 3 / 4; i += TPB) { s4u[i] = gu[i]; s4v[i] = gv[i]; }
        }
        {
            const float4* ga = (const float4*)(x0 + base);
            const float4* gb = (const float4*)(y0 + base);
            float4* s4a = (float4*)sa;
            float4* s4b = (float4*)sb;
            if (t < TPB / 4) { s4a[t] = ga[t]; s4b[t] = gb[t]; }
        }
    } else {
        for (int i = t; i < npair * 9; i += TPB) { sA[i] = x2[base * 9 + i]; sB[i] = y2[base * 9 + i]; }
        for (int i = t; i < npair * 3; i += TPB) { su[i] = x1[base * 3 + i]; sv[i] = y1[base * 3 + i]; }
        for (int i = t; i < npair;     i += TPB) { sa[i] = x0[base + i];     sb[i] = y0[base + i]; }
    }
    __syncthreads();

    // ---- Per-pair compute ----
    float z0 = 0.f, z1[3], z2[9];
    if (t < npair) {
        float a = sa[t], b = sb[t];
        float u[3], v[3], A[9], B[9];
        #pragma unroll
        for (int i = 0; i < 3; i++) { u[i] = su[t * 3 + i]; v[i] = sv[t * 3 + i]; }
        #pragma unroll
        for (int i = 0; i < 9; i++) { A[i] = sA[t * 9 + i]; B[i] = sB[t * 9 + i]; }

        // z0 = a*b + u.v + <A,B>
        z0 = a * b;
        #pragma unroll
        for (int i = 0; i < 3; i++) z0 = fmaf(u[i], v[i], z0);
        #pragma unroll
        for (int i = 0; i < 9; i++) z0 = fmaf(A[i], B[i], z0);

        // z1_i = a*v_i + b*u_i + sum_d u_d B_{d,i} + sum_d A_{i,d} v_d
        #pragma unroll
        for (int i = 0; i < 3; i++) {
            float s = fmaf(a, v[i], b * u[i]);
            #pragma unroll
            for (int d = 0; d < 3; d++) {
                s = fmaf(u[d], B[d * 3 + i], s);
                s = fmaf(A[i * 3 + d], v[d], s);
            }
            z1[i] = s;
        }

        // z2_{ij} = a*B_{ij} + b*A_{ij} + u_i v_j + sum_k A_{ik} B_{kj}
        #pragma unroll
        for (int i = 0; i < 3; i++) {
            #pragma unroll
            for (int j = 0; j < 3; j++) {
                float s = fmaf(a, B[i * 3 + j], b * A[i * 3 + j]);
                s = fmaf(u[i], v[j], s);
                #pragma unroll
                for (int k = 0; k < 3; k++) s = fmaf(A[i * 3 + k], B[k * 3 + j], s);
                z2[i * 3 + j] = s;
            }
        }
    }
    __syncthreads();

    // ---- Stash results in smem (reuse input buffers), then coalesced stores ----
    if (t < npair) {
        sa[t] = z0;
        #pragma unroll
        for (int i = 0; i < 3; i++) su[t * 3 + i] = z1[i];
        #pragma unroll
        for (int i = 0; i < 9; i++) sA[t * 9 + i] = z2[i];
    }
    __syncthreads();

    float* o0 = out;
    float* o1 = out + NC;
    float* o2 = out + 4 * NC;
    if (full) {
        float4* g0 = (float4*)(o0 + base);
        float4* g1 = (float4*)(o1 + base * 3);
        float4* g2 = (float4*)(o2 + base * 9);
        const float4* s40 = (const float4*)sa;
        const float4* s41 = (const float4*)su;
        const float4* s42 = (const float4*)sA;
        if (t < TPB / 4) g0[t] = s40[t];
        #pragma unroll
        for (int i = t; i < TPB * 3 / 4; i += TPB) g1[i] = s41[i];
        #pragma unroll
        for (int i = t; i < TPB * 9 / 4; i += TPB) g2[i] = s42[i];
    } else {
        for (int i = t; i < npair;     i += TPB) o0[base + i]     = sa[i];
        for (int i = t; i < npair * 3; i += TPB) o1[base * 3 + i] = su[i];
        for (int i = t; i < npair * 9; i += TPB) o2[base * 9 + i] = sA[i];
    }
}

extern "C" void kernel_launch(void* const* d_in, const int* in_sizes, int n_in,
                              void* d_out, int out_size)
{
    // out = (z0, z1, z2) concatenated: NC + 3*NC + 9*NC = 13*NC floats
    const long long NC = (long long)out_size / 13;

    // Classify inputs by element count. In both plausible metadata orderings
    // (dict order x0,y0,x1,y1,x2,y2 or alphabetical x0,x1,x2,y0,y1,y2) the
    // x tensor precedes the matching y tensor within each size class.
    const float *x0 = nullptr, *y0 = nullptr, *x1 = nullptr, *y1 = nullptr,
                *x2 = nullptr, *y2 = nullptr;
    for (int i = 0; i < n_in; i++) {
        long long s = in_sizes[i];
        const float* p = (const float*)d_in[i];
        if (s == NC)          { if (!x0) x0 = p; else y0 = p; }
        else if (s == 3 * NC) { if (!x1) x1 = p; else y1 = p; }
        else if (s == 9 * NC) { if (!x2) x2 = p; else y2 = p; }
    }

    const int nblocks = (int)((NC + TPB - 1) / TPB);
    tp_kernel<<<nblocks, TPB>>>(x0, y0, x1, y1, x2, y2, (float*)d_out, NC);
}